// round 9
// baseline (speedup 1.0000x reference)
#include <cuda_runtime.h>

#define BATCH 2
#define SEQ   2048
#define DM    1024
#define NHEAD 16
#define HDIM  64

// Scratch (allocations are forbidden; __device__ globals are the sanctioned path)
__device__ float g_q[BATCH*NHEAD*SEQ*HDIM];     // [B,N,L,H], pre-scaled by H^-0.5
__device__ float g_k[BATCH*NHEAD*SEQ*HDIM];     // [B,N,L,H]
__device__ float g_v[BATCH*NHEAD*SEQ*HDIM];     // [B,N,L,H]
__device__ float g_attn[BATCH*SEQ*NHEAD*HDIM];  // [B,L,N,H] == row-major [4096,1024]

// ---------------------------------------------------------------------------
// C = scale * A(MxK) * B(KxN).  permute=0: row-major [M,N].
// permute=1: write to [B, NHEAD, SEQ, HDIM] (m=b*SEQ+f, col=n*HDIM+h).
// 128x128x16 tile, 256 threads, 8x8 per thread.
// ---------------------------------------------------------------------------
__global__ __launch_bounds__(256) void gemm128(const float* __restrict__ A,
                                               const float* __restrict__ Bm,
                                               float* __restrict__ C,
                                               int M, int K, int Ncol,
                                               float scale, int permute)
{
    __shared__ float As[16][128];
    __shared__ float Bs[16][128];
    const int tid = threadIdx.x;
    const int tx = tid & 15, ty = tid >> 4;
    const int m0 = blockIdx.y * 128, n0 = blockIdx.x * 128;

    float acc[8][8];
#pragma unroll
    for (int i = 0; i < 8; i++)
#pragma unroll
        for (int j = 0; j < 8; j++) acc[i][j] = 0.f;

    for (int k0 = 0; k0 < K; k0 += 16) {
        // A tile: 128 rows x 16 k  (2 float4 per thread, stored transposed)
#pragma unroll
        for (int l = 0; l < 2; l++) {
            int li = tid + l * 256;
            int ar = li >> 2;     // 0..127
            int as = li & 3;      // float4 segment 0..3
            float4 av = *(const float4*)(A + (size_t)(m0 + ar) * K + k0 + as * 4);
            As[as*4+0][ar] = av.x;
            As[as*4+1][ar] = av.y;
            As[as*4+2][ar] = av.z;
            As[as*4+3][ar] = av.w;
        }
        // B tile: 16 k x 128 cols
#pragma unroll
        for (int l = 0; l < 2; l++) {
            int li = tid + l * 256;
            int br = li >> 5;     // 0..15
            int bs = li & 31;     // 0..31
            *(float4*)&Bs[br][bs*4] =
                *(const float4*)(Bm + (size_t)(k0 + br) * Ncol + n0 + bs * 4);
        }
        __syncthreads();

#pragma unroll
        for (int k = 0; k < 16; k++) {
            float af[8], bf[8];
#pragma unroll
            for (int i = 0; i < 8; i++) af[i] = As[k][ty*8 + i];
#pragma unroll
            for (int j = 0; j < 8; j++) bf[j] = Bs[k][tx*8 + j];
#pragma unroll
            for (int i = 0; i < 8; i++)
#pragma unroll
                for (int j = 0; j < 8; j++)
                    acc[i][j] += af[i] * bf[j];
        }
        __syncthreads();
    }

    if (!permute) {
#pragma unroll
        for (int i = 0; i < 8; i++) {
            int m = m0 + ty*8 + i;
#pragma unroll
            for (int j = 0; j < 8; j += 4) {
                float4 v = make_float4(acc[i][j]*scale, acc[i][j+1]*scale,
                                       acc[i][j+2]*scale, acc[i][j+3]*scale);
                *(float4*)(C + (size_t)m * Ncol + n0 + tx*8 + j) = v;
            }
        }
    } else {
        const int c0 = n0 + tx*8;       // 8-aligned -> single head per thread
        const int n  = c0 >> 6;
        const int h0 = c0 & 63;
#pragma unroll
        for (int i = 0; i < 8; i++) {
            int m = m0 + ty*8 + i;
            int b = m >> 11;            // / SEQ
            int f = m & 2047;
            size_t base = ((size_t)(b * NHEAD + n) * SEQ + f) * HDIM + h0;
#pragma unroll
            for (int j = 0; j < 8; j += 4) {
                float4 v = make_float4(acc[i][j]*scale, acc[i][j+1]*scale,
                                       acc[i][j+2]*scale, acc[i][j+3]*scale);
                *(float4*)(C + base + j) = v;
            }
        }
    }
}

// ---------------------------------------------------------------------------
// Flash-style attention: per (b,n) head, 64 query rows per block, streaming
// 64-row K/V tiles with online softmax. 256 threads, 4x4 per thread.
// Q is pre-scaled. Output written as [B, SEQ, NHEAD, HDIM].
// ---------------------------------------------------------------------------
__global__ __launch_bounds__(256) void attn_kernel(const float* __restrict__ Q,
                                                   const float* __restrict__ Kp,
                                                   const float* __restrict__ Vp,
                                                   float* __restrict__ O)
{
    extern __shared__ float smem[];
    float (*Qs)[65] = (float(*)[65])(smem);
    float (*Ks)[65] = (float(*)[65])(smem + 64*65);
    float (*Vs)[65] = (float(*)[65])(smem + 2*64*65);
    float (*Ss)[65] = (float(*)[65])(smem + 3*64*65);

    const int tid = threadIdx.x;
    const int tx = tid & 15, ty = tid >> 4;   // rows ty*4..+3, cols tx*4..+3
    const int f0 = blockIdx.x * 64;
    const int bn = blockIdx.y;                // b*NHEAD + n
    const float* qb = Q  + (size_t)bn * SEQ * HDIM;
    const float* kb = Kp + (size_t)bn * SEQ * HDIM;
    const float* vb = Vp + (size_t)bn * SEQ * HDIM;

    // Load Q tile (64x64) once
#pragma unroll
    for (int l = 0; l < 4; l++) {
        int li = tid + l * 256;
        int r = li >> 4, s = li & 15;
        float4 v = *(const float4*)(qb + (size_t)(f0 + r) * HDIM + s * 4);
        Qs[r][s*4+0] = v.x; Qs[r][s*4+1] = v.y;
        Qs[r][s*4+2] = v.z; Qs[r][s*4+3] = v.w;
    }

    float o[4][4], mrow[4], lrow[4];
#pragma unroll
    for (int i = 0; i < 4; i++) {
        mrow[i] = -1e30f; lrow[i] = 0.f;
#pragma unroll
        for (int j = 0; j < 4; j++) o[i][j] = 0.f;
    }

    for (int t0 = 0; t0 < SEQ; t0 += 64) {
        __syncthreads();   // previous iteration done with Ks/Vs/Ss
        // Load K,V tiles (64x64 each)
#pragma unroll
        for (int l = 0; l < 4; l++) {
            int li = tid + l * 256;
            int r = li >> 4, s = li & 15;
            float4 kv = *(const float4*)(kb + (size_t)(t0 + r) * HDIM + s * 4);
            Ks[r][s*4+0] = kv.x; Ks[r][s*4+1] = kv.y;
            Ks[r][s*4+2] = kv.z; Ks[r][s*4+3] = kv.w;
            float4 vv = *(const float4*)(vb + (size_t)(t0 + r) * HDIM + s * 4);
            Vs[r][s*4+0] = vv.x; Vs[r][s*4+1] = vv.y;
            Vs[r][s*4+2] = vv.z; Vs[r][s*4+3] = vv.w;
        }
        __syncthreads();

        // S = Q * K^T (64x64x64)
        float s_[4][4];
#pragma unroll
        for (int i = 0; i < 4; i++)
#pragma unroll
            for (int j = 0; j < 4; j++) s_[i][j] = 0.f;
#pragma unroll 4
        for (int k = 0; k < HDIM; k++) {
            float qf[4], kf[4];
#pragma unroll
            for (int i = 0; i < 4; i++) qf[i] = Qs[ty*4 + i][k];
#pragma unroll
            for (int j = 0; j < 4; j++) kf[j] = Ks[tx*4 + j][k];
#pragma unroll
            for (int i = 0; i < 4; i++)
#pragma unroll
                for (int j = 0; j < 4; j++)
                    s_[i][j] += qf[i] * kf[j];
        }

        // Online softmax: rows are owned by contiguous 16-lane groups -> shfl
        float alpha[4];
#pragma unroll
        for (int i = 0; i < 4; i++) {
            float mx = fmaxf(fmaxf(s_[i][0], s_[i][1]), fmaxf(s_[i][2], s_[i][3]));
#pragma unroll
            for (int w = 8; w >= 1; w >>= 1)
                mx = fmaxf(mx, __shfl_xor_sync(0xffffffffu, mx, w));
            float mn = fmaxf(mrow[i], mx);
            alpha[i] = __expf(mrow[i] - mn);
            float sum = 0.f;
#pragma unroll
            for (int j = 0; j < 4; j++) {
                s_[i][j] = __expf(s_[i][j] - mn);
                sum += s_[i][j];
            }
#pragma unroll
            for (int w = 8; w >= 1; w >>= 1)
                sum += __shfl_xor_sync(0xffffffffu, sum, w);
            lrow[i] = lrow[i] * alpha[i] + sum;
            mrow[i] = mn;
        }

        // Share P through smem for the PV GEMM
#pragma unroll
        for (int i = 0; i < 4; i++)
#pragma unroll
            for (int j = 0; j < 4; j++) Ss[ty*4 + i][tx*4 + j] = s_[i][j];
        __syncthreads();

        // O = O*alpha + P * V  (64x64x64)
#pragma unroll
        for (int i = 0; i < 4; i++)
#pragma unroll
            for (int j = 0; j < 4; j++) o[i][j] *= alpha[i];
#pragma unroll 4
        for (int t = 0; t < 64; t++) {
            float pf[4], vf[4];
#pragma unroll
            for (int i = 0; i < 4; i++) pf[i] = Ss[ty*4 + i][t];
#pragma unroll
            for (int j = 0; j < 4; j++) vf[j] = Vs[t][tx*4 + j];
#pragma unroll
            for (int i = 0; i < 4; i++)
#pragma unroll
                for (int j = 0; j < 4; j++)
                    o[i][j] += pf[i] * vf[j];
        }
    }

    // Epilogue: normalize, write [B, SEQ, NHEAD, HDIM]
    const int b = bn >> 4, n = bn & 15;
#pragma unroll
    for (int i = 0; i < 4; i++) {
        int f = f0 + ty*4 + i;
        float inv = 1.f / lrow[i];
        float4 v = make_float4(o[i][0]*inv, o[i][1]*inv, o[i][2]*inv, o[i][3]*inv);
        *(float4*)(O + (((size_t)(b * SEQ + f) * NHEAD + n) * HDIM + tx*4)) = v;
    }
}

// ---------------------------------------------------------------------------
extern "C" void kernel_launch(void* const* d_in, const int* in_sizes, int n_in,
                              void* d_out, int out_size)
{
    const float* qin = (const float*)d_in[0];
    const float* kin = (const float*)d_in[1];
    const float* vin = (const float*)d_in[2];
    const float* Wq  = (const float*)d_in[3];
    const float* Wk  = (const float*)d_in[4];
    const float* Wv  = (const float*)d_in[5];
    const float* Wo  = (const float*)d_in[6];
    float* out = (float*)d_out;

    float *gq, *gk, *gv, *ga;
    cudaGetSymbolAddress((void**)&gq, g_q);
    cudaGetSymbolAddress((void**)&gk, g_k);
    cudaGetSymbolAddress((void**)&gv, g_v);
    cudaGetSymbolAddress((void**)&ga, g_attn);

    const int M = BATCH * SEQ;   // 4096
    dim3 gg(DM / 128, M / 128);  // (8, 32)

    // Projections with fused transpose to [B,N,L,H]; Q pre-scaled by 1/sqrt(H)
    gemm128<<<gg, 256>>>(qin, Wq, gq, M, DM, DM, 0.125f, 1);
    gemm128<<<gg, 256>>>(kin, Wk, gk, M, DM, DM, 1.0f,   1);
    gemm128<<<gg, 256>>>(vin, Wv, gv, M, DM, DM, 1.0f,   1);

    // Flash attention
    int smem_bytes = 4 * 64 * 65 * (int)sizeof(float);   // 66,560 B
    cudaFuncSetAttribute(attn_kernel, cudaFuncAttributeMaxDynamicSharedMemorySize,
                         smem_bytes);
    attn_kernel<<<dim3(SEQ / 64, BATCH * NHEAD), 256, smem_bytes>>>(gq, gk, gv, ga);

    // Output projection
    gemm128<<<gg, 256>>>(ga, Wo, out, M, DM, DM, 1.0f, 0);
}

// round 16
// speedup vs baseline: 1.6885x; 1.6885x over previous
#include <cuda_runtime.h>
#include <cuda_bf16.h>
#include <cstdint>

#define BATCH 2
#define SEQ   2048
#define DM    1024
#define NHEAD 16
#define HDIM  64

// Scratch (allocations forbidden; __device__ globals are the sanctioned path)
__device__ float g_q[BATCH*NHEAD*SEQ*HDIM];     // [B,N,L,H], pre-scaled by H^-0.5
__device__ float g_k[BATCH*NHEAD*SEQ*HDIM];     // [B,N,L,H]
__device__ float g_v[BATCH*NHEAD*SEQ*HDIM];     // [B,N,L,H]
__device__ float g_attn[BATCH*SEQ*NHEAD*HDIM];  // [B,L,N,H] == row-major [4096,1024]

// m16n8k16 bf16 MMA, fp32 accum (sm_80+ PTX — compiles on plain sm_103)
__device__ __forceinline__ void mma_bf16(float* d,
                                         uint32_t a0, uint32_t a1, uint32_t a2, uint32_t a3,
                                         uint32_t b0, uint32_t b1)
{
    asm volatile(
        "mma.sync.aligned.m16n8k16.row.col.f32.bf16.bf16.f32 "
        "{%0,%1,%2,%3}, {%4,%5,%6,%7}, {%8,%9}, {%0,%1,%2,%3};"
        : "+f"(d[0]), "+f"(d[1]), "+f"(d[2]), "+f"(d[3])
        : "r"(a0), "r"(a1), "r"(a2), "r"(a3), "r"(b0), "r"(b1));
}

__device__ __forceinline__ __nv_bfloat16 bf_hi(float x) { return __float2bfloat16(x); }
__device__ __forceinline__ __nv_bfloat16 bf_lo(float x) {
    __nv_bfloat16 h = __float2bfloat16(x);
    return __float2bfloat16(x - __bfloat162float(h));
}
__device__ __forceinline__ uint32_t pack_hi(float x, float y) {
    return ((uint32_t)__bfloat16_as_ushort(bf_hi(y)) << 16) | __bfloat16_as_ushort(bf_hi(x));
}
__device__ __forceinline__ uint32_t pack_lo(float x, float y) {
    return ((uint32_t)__bfloat16_as_ushort(bf_lo(y)) << 16) | __bfloat16_as_ushort(bf_lo(x));
}

// ===========================================================================
// mma.sync GEMM (unchanged from audited round-12): C = scale * A x W
// CTA 128x128, 8 warps 4(m)x2(n); bf16 hi/lo, 3 MMAs per product.
// ===========================================================================
__global__ __launch_bounds__(256) void gemm_mma(const float* __restrict__ A,
                                                const float* __restrict__ W,
                                                float* __restrict__ C,
                                                float scale, int permute)
{
    __shared__ __nv_bfloat16 Ah[128][40], Al[128][40];
    __shared__ __nv_bfloat16 Bh[128][40], Bl[128][40];   // [n][k]

    const int tid  = threadIdx.x;
    const int wid  = tid >> 5, lane = tid & 31;
    const int g    = lane >> 2, tig = lane & 3;
    const int wm   = wid & 3,  wn  = wid >> 2;
    const int m0   = blockIdx.y * 128, n0 = blockIdx.x * 128;

    float acc[2][8][4];
#pragma unroll
    for (int mt = 0; mt < 2; mt++)
#pragma unroll
        for (int nt = 0; nt < 8; nt++)
#pragma unroll
            for (int e = 0; e < 4; e++) acc[mt][nt][e] = 0.f;

    for (int k0 = 0; k0 < DM; k0 += 32) {
#pragma unroll
        for (int l = 0; l < 4; l++) {
            int idx = tid + l * 256;
            int row = idx >> 3, seg = idx & 7;
            float4 v = *(const float4*)(A + (size_t)(m0 + row) * DM + k0 + seg * 4);
            *(uint2*)&Ah[row][seg * 4] = make_uint2(pack_hi(v.x, v.y), pack_hi(v.z, v.w));
            *(uint2*)&Al[row][seg * 4] = make_uint2(pack_lo(v.x, v.y), pack_lo(v.z, v.w));
        }
#pragma unroll
        for (int l = 0; l < 16; l++) {
            int idx = tid + l * 256;
            int kk = idx >> 7, n = idx & 127;
            float w = W[(size_t)(k0 + kk) * DM + n0 + n];
            Bh[n][kk] = bf_hi(w);
            Bl[n][kk] = bf_lo(w);
        }
        __syncthreads();

#pragma unroll
        for (int kh = 0; kh < 32; kh += 16) {
            uint32_t ah[2][4], al[2][4];
#pragma unroll
            for (int mt = 0; mt < 2; mt++) {
                int r = wm * 32 + mt * 16;
                ah[mt][0] = *(uint32_t*)&Ah[r + g    ][kh + tig * 2];
                ah[mt][1] = *(uint32_t*)&Ah[r + g + 8][kh + tig * 2];
                ah[mt][2] = *(uint32_t*)&Ah[r + g    ][kh + tig * 2 + 8];
                ah[mt][3] = *(uint32_t*)&Ah[r + g + 8][kh + tig * 2 + 8];
                al[mt][0] = *(uint32_t*)&Al[r + g    ][kh + tig * 2];
                al[mt][1] = *(uint32_t*)&Al[r + g + 8][kh + tig * 2];
                al[mt][2] = *(uint32_t*)&Al[r + g    ][kh + tig * 2 + 8];
                al[mt][3] = *(uint32_t*)&Al[r + g + 8][kh + tig * 2 + 8];
            }
#pragma unroll
            for (int nt = 0; nt < 8; nt++) {
                int c = wn * 64 + nt * 8;
                uint32_t bh0 = *(uint32_t*)&Bh[c + g][kh + tig * 2];
                uint32_t bh1 = *(uint32_t*)&Bh[c + g][kh + tig * 2 + 8];
                uint32_t bl0 = *(uint32_t*)&Bl[c + g][kh + tig * 2];
                uint32_t bl1 = *(uint32_t*)&Bl[c + g][kh + tig * 2 + 8];
#pragma unroll
                for (int mt = 0; mt < 2; mt++) {
                    mma_bf16(acc[mt][nt], ah[mt][0], ah[mt][1], ah[mt][2], ah[mt][3], bh0, bh1);
                    mma_bf16(acc[mt][nt], ah[mt][0], ah[mt][1], ah[mt][2], ah[mt][3], bl0, bl1);
                    mma_bf16(acc[mt][nt], al[mt][0], al[mt][1], al[mt][2], al[mt][3], bh0, bh1);
                }
            }
        }
        __syncthreads();
    }

#pragma unroll
    for (int mt = 0; mt < 2; mt++) {
#pragma unroll
        for (int nt = 0; nt < 8; nt++) {
            int r = m0 + wm * 32 + mt * 16 + g;
            int c = n0 + wn * 64 + nt * 8 + tig * 2;
            float2 v01 = make_float2(acc[mt][nt][0] * scale, acc[mt][nt][1] * scale);
            float2 v23 = make_float2(acc[mt][nt][2] * scale, acc[mt][nt][3] * scale);
            if (!permute) {
                *(float2*)(C + (size_t)r * DM + c)       = v01;
                *(float2*)(C + (size_t)(r + 8) * DM + c) = v23;
            } else {
                int n = c >> 6, h = c & 63;
                int b0_ = r >> 11, f0_ = r & 2047;
                int b1_ = (r + 8) >> 11, f1_ = (r + 8) & 2047;
                *(float2*)(C + ((size_t)(b0_ * NHEAD + n) * SEQ + f0_) * HDIM + h) = v01;
                *(float2*)(C + ((size_t)(b1_ * NHEAD + n) * SEQ + f1_) * HDIM + h) = v23;
            }
        }
    }
}

// ===========================================================================
// Tensor-core flash attention. CTA = 128 thr (4 warps), 64 Q-rows (16/warp).
// S = Q K^T via bf16 hi/lo MMA; online softmax on fragments (quad shfl);
// P·V via P hi/lo + V hi/lo (FA2 frag reuse: S C-frags ARE PV A-frags).
// Q pre-scaled. Output [B, SEQ, NHEAD, HDIM].
// ===========================================================================
__global__ __launch_bounds__(128) void attn_mma(const float* __restrict__ Q,
                                                const float* __restrict__ Kp,
                                                const float* __restrict__ Vp,
                                                float* __restrict__ O)
{
    __shared__ __nv_bfloat16 Kh[64][72], Kl[64][72];     // K tile [t][h]
    __shared__ __nv_bfloat16 Vth[64][72], Vtl[64][72];   // V tile transposed [h][t]

    const int tid = threadIdx.x, wid = tid >> 5, lane = tid & 31;
    const int g = lane >> 2, tig = lane & 3;
    const int f0 = blockIdx.x * 64;
    const int bn = blockIdx.y;
    const float* qb = Q  + (size_t)bn * SEQ * HDIM;
    const float* kb = Kp + (size_t)bn * SEQ * HDIM;
    const float* vb = Vp + (size_t)bn * SEQ * HDIM;

    // Stage Q tile into Kh/Kl, then lift this warp's A-frags into registers.
#pragma unroll
    for (int l = 0; l < 8; l++) {
        int idx = tid + l * 128;          // 0..1023 float4 slots
        int r = idx >> 4, seg = idx & 15;
        float4 v = *(const float4*)(qb + (size_t)(f0 + r) * HDIM + seg * 4);
        *(uint2*)&Kh[r][seg * 4] = make_uint2(pack_hi(v.x, v.y), pack_hi(v.z, v.w));
        *(uint2*)&Kl[r][seg * 4] = make_uint2(pack_lo(v.x, v.y), pack_lo(v.z, v.w));
    }
    __syncthreads();

    uint32_t qh[4][4], ql[4][4];
    {
        const int r = wid * 16;
#pragma unroll
        for (int ks = 0; ks < 4; ks++) {
            qh[ks][0] = *(uint32_t*)&Kh[r + g    ][ks * 16 + tig * 2];
            qh[ks][1] = *(uint32_t*)&Kh[r + g + 8][ks * 16 + tig * 2];
            qh[ks][2] = *(uint32_t*)&Kh[r + g    ][ks * 16 + tig * 2 + 8];
            qh[ks][3] = *(uint32_t*)&Kh[r + g + 8][ks * 16 + tig * 2 + 8];
            ql[ks][0] = *(uint32_t*)&Kl[r + g    ][ks * 16 + tig * 2];
            ql[ks][1] = *(uint32_t*)&Kl[r + g + 8][ks * 16 + tig * 2];
            ql[ks][2] = *(uint32_t*)&Kl[r + g    ][ks * 16 + tig * 2 + 8];
            ql[ks][3] = *(uint32_t*)&Kl[r + g + 8][ks * 16 + tig * 2 + 8];
        }
    }

    float oacc[8][4];
#pragma unroll
    for (int ht = 0; ht < 8; ht++)
#pragma unroll
        for (int e = 0; e < 4; e++) oacc[ht][e] = 0.f;
    float mrun[2] = {-1e30f, -1e30f}, lrun[2] = {0.f, 0.f};

    for (int t0 = 0; t0 < SEQ; t0 += 64) {
        __syncthreads();     // previous tile's MMA reads done / Q-frag staging done
#pragma unroll
        for (int l = 0; l < 8; l++) {
            int idx = tid + l * 128;
            int t = idx >> 4, seg = idx & 15;
            float4 kv = *(const float4*)(kb + (size_t)(t0 + t) * HDIM + seg * 4);
            *(uint2*)&Kh[t][seg * 4] = make_uint2(pack_hi(kv.x, kv.y), pack_hi(kv.z, kv.w));
            *(uint2*)&Kl[t][seg * 4] = make_uint2(pack_lo(kv.x, kv.y), pack_lo(kv.z, kv.w));
            float4 vv = *(const float4*)(vb + (size_t)(t0 + t) * HDIM + seg * 4);
            Vth[seg*4+0][t] = bf_hi(vv.x);  Vtl[seg*4+0][t] = bf_lo(vv.x);
            Vth[seg*4+1][t] = bf_hi(vv.y);  Vtl[seg*4+1][t] = bf_lo(vv.y);
            Vth[seg*4+2][t] = bf_hi(vv.z);  Vtl[seg*4+2][t] = bf_lo(vv.z);
            Vth[seg*4+3][t] = bf_hi(vv.w);  Vtl[seg*4+3][t] = bf_lo(vv.w);
        }
        __syncthreads();

        // S = Q K^T : sacc[nt] covers S cols [nt*8, nt*8+8)
        float sacc[8][4];
#pragma unroll
        for (int nt = 0; nt < 8; nt++)
#pragma unroll
            for (int e = 0; e < 4; e++) sacc[nt][e] = 0.f;
#pragma unroll
        for (int ks = 0; ks < 4; ks++) {
#pragma unroll
            for (int nt = 0; nt < 8; nt++) {
                uint32_t bh0 = *(uint32_t*)&Kh[nt*8 + g][ks*16 + tig*2];
                uint32_t bh1 = *(uint32_t*)&Kh[nt*8 + g][ks*16 + tig*2 + 8];
                uint32_t bl0 = *(uint32_t*)&Kl[nt*8 + g][ks*16 + tig*2];
                uint32_t bl1 = *(uint32_t*)&Kl[nt*8 + g][ks*16 + tig*2 + 8];
                mma_bf16(sacc[nt], qh[ks][0], qh[ks][1], qh[ks][2], qh[ks][3], bh0, bh1);
                mma_bf16(sacc[nt], qh[ks][0], qh[ks][1], qh[ks][2], qh[ks][3], bl0, bl1);
                mma_bf16(sacc[nt], ql[ks][0], ql[ks][1], ql[ks][2], ql[ks][3], bh0, bh1);
            }
        }

        // Online softmax on fragments. Row-half 0 = row g (c0,c1), 1 = row g+8 (c2,c3).
        float alpha[2];
#pragma unroll
        for (int h = 0; h < 2; h++) {
            float mx = -1e30f;
#pragma unroll
            for (int nt = 0; nt < 8; nt++)
                mx = fmaxf(mx, fmaxf(sacc[nt][h*2], sacc[nt][h*2+1]));
            mx = fmaxf(mx, __shfl_xor_sync(0xffffffffu, mx, 1));
            mx = fmaxf(mx, __shfl_xor_sync(0xffffffffu, mx, 2));
            float mn = fmaxf(mrun[h], mx);
            alpha[h] = __expf(mrun[h] - mn);
            mrun[h] = mn;
            float sum = 0.f;
#pragma unroll
            for (int nt = 0; nt < 8; nt++) {
                float p0 = __expf(sacc[nt][h*2]   - mn);
                float p1 = __expf(sacc[nt][h*2+1] - mn);
                sacc[nt][h*2] = p0; sacc[nt][h*2+1] = p1;
                sum += p0 + p1;
            }
            sum += __shfl_xor_sync(0xffffffffu, sum, 1);
            sum += __shfl_xor_sync(0xffffffffu, sum, 2);
            lrun[h] = lrun[h] * alpha[h] + sum;
        }
#pragma unroll
        for (int ht = 0; ht < 8; ht++) {
            oacc[ht][0] *= alpha[0]; oacc[ht][1] *= alpha[0];
            oacc[ht][2] *= alpha[1]; oacc[ht][3] *= alpha[1];
        }

        // P C-frags -> A-frags for PV (FA2 mapping), hi/lo split.
        uint32_t pfh[4][4], pfl[4][4];
#pragma unroll
        for (int kt = 0; kt < 4; kt++) {
            pfh[kt][0] = pack_hi(sacc[2*kt][0],   sacc[2*kt][1]);
            pfh[kt][1] = pack_hi(sacc[2*kt][2],   sacc[2*kt][3]);
            pfh[kt][2] = pack_hi(sacc[2*kt+1][0], sacc[2*kt+1][1]);
            pfh[kt][3] = pack_hi(sacc[2*kt+1][2], sacc[2*kt+1][3]);
            pfl[kt][0] = pack_lo(sacc[2*kt][0],   sacc[2*kt][1]);
            pfl[kt][1] = pack_lo(sacc[2*kt][2],   sacc[2*kt][3]);
            pfl[kt][2] = pack_lo(sacc[2*kt+1][0], sacc[2*kt+1][1]);
            pfl[kt][3] = pack_lo(sacc[2*kt+1][2], sacc[2*kt+1][3]);
        }

        // O += P V : oacc[ht] covers H cols [ht*8, ht*8+8)
#pragma unroll
        for (int ht = 0; ht < 8; ht++) {
#pragma unroll
            for (int kt = 0; kt < 4; kt++) {
                uint32_t bh0 = *(uint32_t*)&Vth[ht*8 + g][kt*16 + tig*2];
                uint32_t bh1 = *(uint32_t*)&Vth[ht*8 + g][kt*16 + tig*2 + 8];
                uint32_t bl0 = *(uint32_t*)&Vtl[ht*8 + g][kt*16 + tig*2];
                uint32_t bl1 = *(uint32_t*)&Vtl[ht*8 + g][kt*16 + tig*2 + 8];
                mma_bf16(oacc[ht], pfh[kt][0], pfh[kt][1], pfh[kt][2], pfh[kt][3], bh0, bh1);
                mma_bf16(oacc[ht], pfl[kt][0], pfl[kt][1], pfl[kt][2], pfl[kt][3], bh0, bh1);
                mma_bf16(oacc[ht], pfh[kt][0], pfh[kt][1], pfh[kt][2], pfh[kt][3], bl0, bl1);
            }
        }
    }

    // Epilogue: normalize, write [B, SEQ, NHEAD, HDIM]
    const int b = bn >> 4, n = bn & 15;
    const int r0 = f0 + wid * 16 + g, r1 = r0 + 8;
    const float inv0 = 1.f / lrun[0], inv1 = 1.f / lrun[1];
#pragma unroll
    for (int ht = 0; ht < 8; ht++) {
        int h = ht * 8 + tig * 2;
        *(float2*)(O + ((size_t)(b * SEQ + r0) * NHEAD + n) * HDIM + h) =
            make_float2(oacc[ht][0] * inv0, oacc[ht][1] * inv0);
        *(float2*)(O + ((size_t)(b * SEQ + r1) * NHEAD + n) * HDIM + h) =
            make_float2(oacc[ht][2] * inv1, oacc[ht][3] * inv1);
    }
}

// ---------------------------------------------------------------------------
extern "C" void kernel_launch(void* const* d_in, const int* in_sizes, int n_in,
                              void* d_out, int out_size)
{
    const float* qin = (const float*)d_in[0];
    const float* kin = (const float*)d_in[1];
    const float* vin = (const float*)d_in[2];
    const float* Wq  = (const float*)d_in[3];
    const float* Wk  = (const float*)d_in[4];
    const float* Wv  = (const float*)d_in[5];
    const float* Wo  = (const float*)d_in[6];
    float* out = (float*)d_out;

    float *gq, *gk, *gv, *ga;
    cudaGetSymbolAddress((void**)&gq, g_q);
    cudaGetSymbolAddress((void**)&gk, g_k);
    cudaGetSymbolAddress((void**)&gv, g_v);
    cudaGetSymbolAddress((void**)&ga, g_attn);

    dim3 gg(DM / 128, (BATCH * SEQ) / 128);   // (8, 32)

    // Projections via mma.sync bf16 hi/lo; Q pre-scaled by 1/sqrt(H)
    gemm_mma<<<gg, 256>>>(qin, Wq, gq, 0.125f, 1);
    gemm_mma<<<gg, 256>>>(kin, Wk, gk, 1.0f,   1);
    gemm_mma<<<gg, 256>>>(vin, Wv, gv, 1.0f,   1);

    // Tensor-core flash attention
    attn_mma<<<dim3(SEQ / 64, BATCH * NHEAD), 128>>>(gq, gk, gv, ga);

    // Output projection via mma.sync
    gemm_mma<<<gg, 256>>>(ga, Wo, out, 1.0f, 0);
}